// round 14
// baseline (speedup 1.0000x reference)
#include <cuda_runtime.h>
#include <cstdint>

// Depth-to-space r=4, x-major channel ordering:
//   out[b, c, y, x] = in[b, c*16 + 4*(x%4) + (y%4), y/4, x/4]
// in : (16, 4096, 32, 32) fp32  -> 256 MB
// out: (16, 256, 128, 128) fp32 -> 256 MB
//
// FINAL champion — reproduced 6x at 78.1-78.9us kernel (6.17-6.24 TB/s,
// ~78% of HBM spec = the measured mixed read/write DRAM ceiling):
//  - 256-bit v8.f32 loads/stores: every access is a full 32B sector
//  - per thread: 4 loads (one per xr source channel, 32B each) + 4 stores
//    writing 128B dense; a warp writes 8 consecutive output rows (4KB)
//  - no cache hints, natural register allocation / occupancy
//
// Search space closed (rounds 3-13): dense-loads/scattered-stores remap,
// 2x MLP, evict_first hints, reg-capped occupancy, smem staging, TMA
// staging, CTA geometry, launch-order swizzle — all neutral or negative.
// Traffic is irreducible (bijective permutation, no reuse), the
// load/store density conflict is structural, and every exchange mechanism
// to resolve it costs more on-chip than it recovers at DRAM.
// Single-bottleneck kernel: DRAM ~78%, issue 4.3%, compute 3%.

__global__ void __launch_bounds__(256) scale_transfer_v8_kernel(
    const float* __restrict__ in, float* __restrict__ out)
{
    unsigned tid = blockIdx.x * blockDim.x + threadIdx.x;
    // tid layout: b[4] c[8] y[7] xq8[2]  -> 16*256*128*4 = 2,097,152 threads
    unsigned xq = tid & 3;            // 8-float group within 32-float input row
    unsigned y  = (tid >> 2) & 127;
    unsigned c  = (tid >> 9) & 255;
    unsigned b  = tid >> 17;

    unsigned yr = y & 3;
    unsigned yb = y >> 2;

    // input float index; channel stride for xr is 4 channels = 4096 floats
    const float* p =
        in + (((b * 4096u + c * 16u + yr) * 32u + yb) * 32u + xq * 8u);

    float r[4][8];
#pragma unroll
    for (int xr = 0; xr < 4; xr++) {
        const float* q = p + xr * 4096;
        asm volatile(
            "ld.global.nc.v8.f32 {%0,%1,%2,%3,%4,%5,%6,%7}, [%8];"
            : "=f"(r[xr][0]), "=f"(r[xr][1]), "=f"(r[xr][2]), "=f"(r[xr][3]),
              "=f"(r[xr][4]), "=f"(r[xr][5]), "=f"(r[xr][6]), "=f"(r[xr][7])
            : "l"(q));
    }

    // output: 32 consecutive floats (x = xq*32 .. xq*32+31) of row (b,c,y)
    float* o = out + (((b * 256u + c) * 128u + y) * 128u + xq * 32u);

#pragma unroll
    for (int j = 0; j < 4; j++) {
        // out local x = 4*i + xr, group j covers i = 2j, 2j+1
        int i0 = 2 * j, i1 = 2 * j + 1;
        asm volatile(
            "st.global.v8.f32 [%0], {%1,%2,%3,%4,%5,%6,%7,%8};"
            :
            : "l"(o + j * 8),
              "f"(r[0][i0]), "f"(r[1][i0]), "f"(r[2][i0]), "f"(r[3][i0]),
              "f"(r[0][i1]), "f"(r[1][i1]), "f"(r[2][i1]), "f"(r[3][i1])
            : "memory");
    }
}

extern "C" void kernel_launch(void* const* d_in, const int* in_sizes, int n_in,
                              void* d_out, int out_size)
{
    const float* in = (const float*)d_in[0];
    float* out = (float*)d_out;

    const int total_threads = 16 * 256 * 128 * 4;  // 2,097,152
    const int block = 256;
    const int grid = total_threads / block;        // 8192

    scale_transfer_v8_kernel<<<grid, block>>>(in, out);
}

// round 15
// speedup vs baseline: 1.0047x; 1.0047x over previous
#include <cuda_runtime.h>
#include <cstdint>

// Depth-to-space r=4, x-major channel ordering:
//   out[b, c, y, x] = in[b, c*16 + 4*(x%4) + (y%4), y/4, x/4]
// in : (16, 4096, 32, 32) fp32  -> 256 MB
// out: (16, 256, 128, 128) fp32 -> 256 MB
//
// FINAL champion — reproduced 7x at 77.3-78.9us kernel (6.17-6.30 TB/s,
// ~78-79% of HBM spec = the measured mixed read/write DRAM ceiling):
//  - 256-bit v8.f32 loads/stores: every access is a full 32B sector
//  - per thread: 4 loads (one per xr source channel, 32B each) + 4 stores
//    writing 128B dense; a warp writes 8 consecutive output rows (4KB)
//  - no cache hints, natural register allocation / occupancy
//
// Search space closed (rounds 3-13): dense-loads/scattered-stores remap,
// 2x MLP, evict_first hints, reg-capped occupancy, smem staging, TMA
// staging, CTA geometry, launch-order swizzle — all neutral or negative.
// Traffic is irreducible (bijective permutation, no reuse), the
// load/store density conflict is structural, and every exchange mechanism
// to resolve it costs more on-chip than it recovers at DRAM.
// Single-bottleneck kernel: DRAM ~78-79%, issue 4.3%, compute 3%.

__global__ void __launch_bounds__(256) scale_transfer_v8_kernel(
    const float* __restrict__ in, float* __restrict__ out)
{
    unsigned tid = blockIdx.x * blockDim.x + threadIdx.x;
    // tid layout: b[4] c[8] y[7] xq8[2]  -> 16*256*128*4 = 2,097,152 threads
    unsigned xq = tid & 3;            // 8-float group within 32-float input row
    unsigned y  = (tid >> 2) & 127;
    unsigned c  = (tid >> 9) & 255;
    unsigned b  = tid >> 17;

    unsigned yr = y & 3;
    unsigned yb = y >> 2;

    // input float index; channel stride for xr is 4 channels = 4096 floats
    const float* p =
        in + (((b * 4096u + c * 16u + yr) * 32u + yb) * 32u + xq * 8u);

    float r[4][8];
#pragma unroll
    for (int xr = 0; xr < 4; xr++) {
        const float* q = p + xr * 4096;
        asm volatile(
            "ld.global.nc.v8.f32 {%0,%1,%2,%3,%4,%5,%6,%7}, [%8];"
            : "=f"(r[xr][0]), "=f"(r[xr][1]), "=f"(r[xr][2]), "=f"(r[xr][3]),
              "=f"(r[xr][4]), "=f"(r[xr][5]), "=f"(r[xr][6]), "=f"(r[xr][7])
            : "l"(q));
    }

    // output: 32 consecutive floats (x = xq*32 .. xq*32+31) of row (b,c,y)
    float* o = out + (((b * 256u + c) * 128u + y) * 128u + xq * 32u);

#pragma unroll
    for (int j = 0; j < 4; j++) {
        // out local x = 4*i + xr, group j covers i = 2j, 2j+1
        int i0 = 2 * j, i1 = 2 * j + 1;
        asm volatile(
            "st.global.v8.f32 [%0], {%1,%2,%3,%4,%5,%6,%7,%8};"
            :
            : "l"(o + j * 8),
              "f"(r[0][i0]), "f"(r[1][i0]), "f"(r[2][i0]), "f"(r[3][i0]),
              "f"(r[0][i1]), "f"(r[1][i1]), "f"(r[2][i1]), "f"(r[3][i1])
            : "memory");
    }
}

extern "C" void kernel_launch(void* const* d_in, const int* in_sizes, int n_in,
                              void* d_out, int out_size)
{
    const float* in = (const float*)d_in[0];
    float* out = (float*)d_out;

    const int total_threads = 16 * 256 * 128 * 4;  // 2,097,152
    const int block = 256;
    const int grid = total_threads / block;        // 8192

    scale_transfer_v8_kernel<<<grid, block>>>(in, out);
}